// round 4
// baseline (speedup 1.0000x reference)
#include <cuda_runtime.h>
#include <cstdint>
#include <math.h>

// Problem constants: B=2, S=2048, HIDDEN=4096, NH=32, D=128
// proj layout: [token(4096), 12288] where cols [0,4096)=Q, [4096,8192)=K, [8192,12288)=V
// attn layout: [token(4096), 4096] = [b,s,h*128+d]

static __device__ float g_proj[(size_t)4096 * 12288];   // 201 MB scratch
static __device__ float g_attn[(size_t)4096 * 4096];    //  67 MB scratch

#define NEG_BIG (-1e30f)

__device__ __forceinline__ unsigned f2tf(float x) {
    unsigned u;
    asm("cvt.rna.tf32.f32 %0, %1;" : "=r"(u) : "f"(x));
    return u;
}

__device__ __forceinline__ void mma_tf32(float* d, const unsigned* a, const unsigned* b) {
    asm volatile(
        "mma.sync.aligned.m16n8k8.row.col.f32.tf32.tf32.f32 "
        "{%0,%1,%2,%3}, {%4,%5,%6,%7}, {%8,%9}, {%0,%1,%2,%3};\n"
        : "+f"(d[0]), "+f"(d[1]), "+f"(d[2]), "+f"(d[3])
        : "r"(a[0]), "r"(a[1]), "r"(a[2]), "r"(a[3]), "r"(b[0]), "r"(b[1]));
}

__device__ __forceinline__ void st4_tf(float* p, float4 v) {
    p[0] = __uint_as_float(f2tf(v.x));
    p[1] = __uint_as_float(f2tf(v.y));
    p[2] = __uint_as_float(f2tf(v.z));
    p[3] = __uint_as_float(f2tf(v.w));
}

// ---------------------------------------------------------------------------
// GEMM: C[M,N] = A[M,K] @ B[N,K]^T   (both operands row-major, K contiguous)
// BM=BN=128, BK=32, 256 threads (8 warps: 2x4), tf32 mma m16n8k8.
// All dims divisible by 128/32 for this problem; no bounds checks.
// ---------------------------------------------------------------------------
__global__ __launch_bounds__(256) void gemm_tf32_kernel(
    float* __restrict__ C, const float* __restrict__ A, const float* __restrict__ B,
    int M, int N, int K)
{
    __shared__ float sA[128 * 36];  // [m][k], pad 36 (36 mod 32 = 4 -> conflict-free frags)
    __shared__ float sB[128 * 36];  // [n][k]

    // Swizzled CTA mapping (GROUP_M=8) for L2 reuse
    int num_m = M >> 7, num_n = N >> 7;
    const int GROUP = 8;
    int pid   = blockIdx.x;
    int width = GROUP * num_n;
    int gidx  = pid / width;
    int first_m = gidx * GROUP;
    int gsz   = min(GROUP, num_m - first_m);
    int pin   = pid % width;
    int pm    = first_m + (pin % gsz);
    int pn    = pin / gsz;

    int tid  = threadIdx.x;
    int lane = tid & 31, w = tid >> 5;
    int g = lane >> 2, c = lane & 3;
    int wm = (w >> 2) * 64;   // warp row offset (0 or 64)
    int wn = (w & 3) * 32;    // warp col offset (0..96)

    const float* Ab = A + (size_t)pm * 128 * K;
    const float* Bb = B + (size_t)pn * 128 * K;

    float acc[4][4][4];
    #pragma unroll
    for (int i = 0; i < 4; i++)
        #pragma unroll
        for (int j = 0; j < 4; j++)
            #pragma unroll
            for (int q = 0; q < 4; q++) acc[i][j][q] = 0.f;

    for (int kb = 0; kb < K; kb += 32) {
        // Load 128x32 tiles of A and B (float4, tf32-convert on store)
        #pragma unroll
        for (int i = 0; i < 4; i++) {
            int idx = tid + i * 256;          // 0..1023
            int r = idx >> 3, c4 = (idx & 7) << 2;
            float4 va = *reinterpret_cast<const float4*>(Ab + (size_t)r * K + kb + c4);
            float4 vb = *reinterpret_cast<const float4*>(Bb + (size_t)r * K + kb + c4);
            st4_tf(&sA[r * 36 + c4], va);
            st4_tf(&sB[r * 36 + c4], vb);
        }
        __syncthreads();

        #pragma unroll
        for (int ks = 0; ks < 4; ks++) {
            int k0 = ks * 8;
            unsigned afr[4][4], bfr[4][2];
            #pragma unroll
            for (int mi = 0; mi < 4; mi++) {
                int r0 = wm + mi * 16 + g;
                afr[mi][0] = __float_as_uint(sA[r0 * 36 + k0 + c]);
                afr[mi][1] = __float_as_uint(sA[(r0 + 8) * 36 + k0 + c]);
                afr[mi][2] = __float_as_uint(sA[r0 * 36 + k0 + c + 4]);
                afr[mi][3] = __float_as_uint(sA[(r0 + 8) * 36 + k0 + c + 4]);
            }
            #pragma unroll
            for (int nj = 0; nj < 4; nj++) {
                int rb = wn + nj * 8 + g;
                bfr[nj][0] = __float_as_uint(sB[rb * 36 + k0 + c]);
                bfr[nj][1] = __float_as_uint(sB[rb * 36 + k0 + c + 4]);
            }
            #pragma unroll
            for (int mi = 0; mi < 4; mi++)
                #pragma unroll
                for (int nj = 0; nj < 4; nj++)
                    mma_tf32(acc[mi][nj], afr[mi], bfr[nj]);
        }
        __syncthreads();
    }

    // Epilogue: C fragment layout -> gmem
    #pragma unroll
    for (int mi = 0; mi < 4; mi++) {
        int r0 = pm * 128 + wm + mi * 16 + g;
        #pragma unroll
        for (int nj = 0; nj < 4; nj++) {
            int col = pn * 128 + wn + nj * 8 + 2 * c;
            C[(size_t)r0 * N + col]           = acc[mi][nj][0];
            C[(size_t)r0 * N + col + 1]       = acc[mi][nj][1];
            C[(size_t)(r0 + 8) * N + col]     = acc[mi][nj][2];
            C[(size_t)(r0 + 8) * N + col + 1] = acc[mi][nj][3];
        }
    }
}

// ---------------------------------------------------------------------------
// RoPE in-place on Q and K sections of proj. One thread per (token, head, d<64).
// ---------------------------------------------------------------------------
__global__ void rope_kernel(float* __restrict__ proj) {
    int idx = blockIdx.x * blockDim.x + threadIdx.x;
    if (idx >= 4096 * 32 * 64) return;
    int d   = idx & 63;
    int h   = (idx >> 6) & 31;
    int tok = idx >> 11;
    int pos = tok & 2047;

    float e   = (float)(2 * d) * (1.0f / 128.0f);
    float inv = 1.0f / powf(10000.0f, e);
    float ang = (float)pos * inv;
    float sn, cs;
    sincosf(ang, &sn, &cs);

    size_t base = (size_t)tok * 12288 + h * 128 + d;
    float q0 = proj[base], q1 = proj[base + 64];
    proj[base]      = q0 * cs - q1 * sn;
    proj[base + 64] = q1 * cs + q0 * sn;
    size_t kb = base + 4096;
    float k0 = proj[kb], k1 = proj[kb + 64];
    proj[kb]      = k0 * cs - k1 * sn;
    proj[kb + 64] = k1 * cs + k0 * sn;
}

// ---------------------------------------------------------------------------
// Flash attention (causal, online softmax, fp32 accum, tf32 mma).
// Grid: (32 m-tiles, 64 b*h). 128 threads (4 warps, 16 q-rows each).
// BM=64 q rows, BN=64 kv cols per iteration, D=128.
// ---------------------------------------------------------------------------
#define QP 132
#define KPD 132
#define VP 136
#define FLASH_SMEM ((64 * QP + 64 * KPD + 64 * VP) * 4)

__global__ __launch_bounds__(128) void flash_kernel(
    const float* __restrict__ proj, float* __restrict__ outp)
{
    extern __shared__ float smem[];
    float* sQ = smem;
    float* sK = sQ + 64 * QP;
    float* sV = sK + 64 * KPD;

    int mt = blockIdx.x;
    int bh = blockIdx.y;
    int b  = bh >> 5, h = bh & 31;
    int tid = threadIdx.x, w = tid >> 5, lane = tid & 31;
    int g = lane >> 2, c = lane & 3;

    const float* base = proj + (size_t)b * 2048 * 12288 + h * 128;

    // Load Q tile [64,128] once (tf32-converted)
    #pragma unroll
    for (int i = 0; i < 16; i++) {
        int idx = tid + i * 128;
        int r = idx >> 5, c4 = (idx & 31) << 2;
        float4 v = *reinterpret_cast<const float4*>(base + (size_t)(mt * 64 + r) * 12288 + c4);
        st4_tf(&sQ[r * QP + c4], v);
    }

    float o[16][4];
    #pragma unroll
    for (int i = 0; i < 16; i++)
        #pragma unroll
        for (int q = 0; q < 4; q++) o[i][q] = 0.f;
    float m0 = NEG_BIG, m1 = NEG_BIG, l0 = 0.f, l1 = 0.f;

    int qr0 = mt * 64 + w * 16 + g;
    int qr1 = qr0 + 8;
    const float SCALE = 0.08838834764831845f;  // 1/sqrt(128)

    for (int jt = 0; jt <= mt; jt++) {
        __syncthreads();  // protect previous iteration's smem reads
        // Load K,V tiles [64,128]
        #pragma unroll
        for (int i = 0; i < 16; i++) {
            int idx = tid + i * 128;
            int r = idx >> 5, c4 = (idx & 31) << 2;
            size_t row_off = (size_t)(jt * 64 + r) * 12288 + c4;
            float4 vk = *reinterpret_cast<const float4*>(base + 4096 + row_off);
            float4 vv = *reinterpret_cast<const float4*>(base + 8192 + row_off);
            st4_tf(&sK[r * KPD + c4], vk);
            st4_tf(&sV[r * VP + c4], vv);
        }
        __syncthreads();

        // S = Q @ K^T : per warp 16x64, 8 n-frags, 16 k-steps
        float s[8][4];
        #pragma unroll
        for (int nj = 0; nj < 8; nj++)
            #pragma unroll
            for (int q = 0; q < 4; q++) s[nj][q] = 0.f;

        int r0 = w * 16 + g;
        #pragma unroll
        for (int ks = 0; ks < 16; ks++) {
            int k0 = ks * 8;
            unsigned a[4];
            a[0] = __float_as_uint(sQ[r0 * QP + k0 + c]);
            a[1] = __float_as_uint(sQ[(r0 + 8) * QP + k0 + c]);
            a[2] = __float_as_uint(sQ[r0 * QP + k0 + c + 4]);
            a[3] = __float_as_uint(sQ[(r0 + 8) * QP + k0 + c + 4]);
            #pragma unroll
            for (int nj = 0; nj < 8; nj++) {
                unsigned bb[2];
                int rb = nj * 8 + g;
                bb[0] = __float_as_uint(sK[rb * KPD + k0 + c]);
                bb[1] = __float_as_uint(sK[rb * KPD + k0 + c + 4]);
                mma_tf32(s[nj], a, bb);
            }
        }

        // scale + causal mask
        #pragma unroll
        for (int nj = 0; nj < 8; nj++) {
            int c0 = jt * 64 + nj * 8 + 2 * c;
            int c1 = c0 + 1;
            s[nj][0] = (c0 <= qr0) ? s[nj][0] * SCALE : NEG_BIG;
            s[nj][1] = (c1 <= qr0) ? s[nj][1] * SCALE : NEG_BIG;
            s[nj][2] = (c0 <= qr1) ? s[nj][2] * SCALE : NEG_BIG;
            s[nj][3] = (c1 <= qr1) ? s[nj][3] * SCALE : NEG_BIG;
        }

        // row max (reduce across the 4 lanes sharing each row)
        float rm0 = NEG_BIG, rm1 = NEG_BIG;
        #pragma unroll
        for (int nj = 0; nj < 8; nj++) {
            rm0 = fmaxf(rm0, fmaxf(s[nj][0], s[nj][1]));
            rm1 = fmaxf(rm1, fmaxf(s[nj][2], s[nj][3]));
        }
        rm0 = fmaxf(rm0, __shfl_xor_sync(0xffffffffu, rm0, 1));
        rm0 = fmaxf(rm0, __shfl_xor_sync(0xffffffffu, rm0, 2));
        rm1 = fmaxf(rm1, __shfl_xor_sync(0xffffffffu, rm1, 1));
        rm1 = fmaxf(rm1, __shfl_xor_sync(0xffffffffu, rm1, 2));

        float mn0 = fmaxf(m0, rm0), mn1 = fmaxf(m1, rm1);
        float al0 = __expf(m0 - mn0), al1 = __expf(m1 - mn1);
        m0 = mn0; m1 = mn1;

        // P = exp(S - m), row sums
        float rs0 = 0.f, rs1 = 0.f;
        #pragma unroll
        for (int nj = 0; nj < 8; nj++) {
            s[nj][0] = __expf(s[nj][0] - m0);
            s[nj][1] = __expf(s[nj][1] - m0);
            s[nj][2] = __expf(s[nj][2] - m1);
            s[nj][3] = __expf(s[nj][3] - m1);
            rs0 += s[nj][0] + s[nj][1];
            rs1 += s[nj][2] + s[nj][3];
        }
        rs0 += __shfl_xor_sync(0xffffffffu, rs0, 1);
        rs0 += __shfl_xor_sync(0xffffffffu, rs0, 2);
        rs1 += __shfl_xor_sync(0xffffffffu, rs1, 1);
        rs1 += __shfl_xor_sync(0xffffffffu, rs1, 2);
        l0 = l0 * al0 + rs0;
        l1 = l1 * al1 + rs1;

        // rescale O accumulators
        #pragma unroll
        for (int nf = 0; nf < 16; nf++) {
            o[nf][0] *= al0; o[nf][1] *= al0;
            o[nf][2] *= al1; o[nf][3] *= al1;
        }

        // O += P @ V : convert C-layout P-frags to A-layout via shuffles
        int src  = (lane & ~3) | (c >> 1);
        int src2 = src + 2;
        bool odd = (c & 1) != 0;
        #pragma unroll
        for (int kk = 0; kk < 8; kk++) {
            float e0 = __shfl_sync(0xffffffffu, s[kk][0], src);
            float f0 = __shfl_sync(0xffffffffu, s[kk][1], src);
            float e1 = __shfl_sync(0xffffffffu, s[kk][2], src);
            float f1 = __shfl_sync(0xffffffffu, s[kk][3], src);
            float e2 = __shfl_sync(0xffffffffu, s[kk][0], src2);
            float f2 = __shfl_sync(0xffffffffu, s[kk][1], src2);
            float e3 = __shfl_sync(0xffffffffu, s[kk][2], src2);
            float f3 = __shfl_sync(0xffffffffu, s[kk][3], src2);
            unsigned a[4];
            a[0] = f2tf(odd ? f0 : e0);
            a[1] = f2tf(odd ? f1 : e1);
            a[2] = f2tf(odd ? f2 : e2);
            a[3] = f2tf(odd ? f3 : e3);
            #pragma unroll
            for (int nf = 0; nf < 16; nf++) {
                unsigned bb[2];
                bb[0] = __float_as_uint(sV[(kk * 8 + c) * VP + nf * 8 + g]);
                bb[1] = __float_as_uint(sV[(kk * 8 + c + 4) * VP + nf * 8 + g]);
                mma_tf32(o[nf], a, bb);
            }
        }
    }

    // Normalize and store: out[token, h*128 + d]
    float i0 = 1.0f / l0, i1 = 1.0f / l1;
    int tk0 = b * 2048 + mt * 64 + w * 16 + g;
    int tk1 = tk0 + 8;
    size_t ob0 = (size_t)tk0 * 4096 + h * 128;
    size_t ob1 = (size_t)tk1 * 4096 + h * 128;
    #pragma unroll
    for (int nf = 0; nf < 16; nf++) {
        int col = nf * 8 + 2 * c;
        outp[ob0 + col]     = o[nf][0] * i0;
        outp[ob0 + col + 1] = o[nf][1] * i0;
        outp[ob1 + col]     = o[nf][2] * i1;
        outp[ob1 + col + 1] = o[nf][3] * i1;
    }
}

// ---------------------------------------------------------------------------
extern "C" void kernel_launch(void* const* d_in, const int* in_sizes, int n_in,
                              void* d_out, int out_size)
{
    (void)in_sizes; (void)n_in; (void)out_size;
    const float* X  = (const float*)d_in[0];  // hidden_states [2,2048,4096]
    // d_in[1] attention_mask (pure causal, implemented analytically)
    // d_in[2] position_ids (arange, implemented analytically)
    const float* Wp = (const float*)d_in[3];  // W_pack [12288,4096]
    const float* Wo = (const float*)d_in[4];  // W_o    [4096,4096]
    float* out = (float*)d_out;

    float *proj = nullptr, *attn = nullptr;
    cudaGetSymbolAddress((void**)&proj, g_proj);
    cudaGetSymbolAddress((void**)&attn, g_attn);

    cudaFuncSetAttribute(flash_kernel, cudaFuncAttributeMaxDynamicSharedMemorySize, FLASH_SMEM);

    // 1) QKV projection: proj = X @ Wp^T   (M=4096, N=12288, K=4096)
    gemm_tf32_kernel<<<32 * 96, 256>>>(proj, X, Wp, 4096, 12288, 4096);

    // 2) RoPE in-place on Q,K
    rope_kernel<<<(4096 * 32 * 64) / 256, 256>>>(proj);

    // 3) Flash attention -> attn [4096, 4096]
    flash_kernel<<<dim3(32, 64), 128, FLASH_SMEM>>>(proj, attn);

    // 4) Output projection: out = attn @ Wo^T  (M=4096, N=4096, K=4096)
    gemm_tf32_kernel<<<32 * 32, 256>>>(out, attn, Wo, 4096, 4096, 4096);
}

// round 5
// speedup vs baseline: 1.5968x; 1.5968x over previous
#include <cuda_runtime.h>
#include <cstdint>
#include <math.h>

// Problem constants: B=2, S=2048, HIDDEN=4096, NH=32, D=128
// proj layout: [token(4096), 12288] cols [0,4096)=Q, [4096,8192)=K, [8192,12288)=V
// attn layout: [token(4096), 4096]

static __device__ float g_proj[(size_t)4096 * 12288];   // 201 MB scratch
static __device__ float g_attn[(size_t)4096 * 4096];    //  67 MB scratch

#define NEG_BIG (-1e30f)

__device__ __forceinline__ unsigned f2tf(float x) {
    unsigned u;
    asm("cvt.rna.tf32.f32 %0, %1;" : "=r"(u) : "f"(x));
    return u;
}

__device__ __forceinline__ void mma_tf32(float* d, const unsigned* a, const unsigned* b) {
    asm volatile(
        "mma.sync.aligned.m16n8k8.row.col.f32.tf32.tf32.f32 "
        "{%0,%1,%2,%3}, {%4,%5,%6,%7}, {%8,%9}, {%0,%1,%2,%3};\n"
        : "+f"(d[0]), "+f"(d[1]), "+f"(d[2]), "+f"(d[3])
        : "r"(a[0]), "r"(a[1]), "r"(a[2]), "r"(a[3]), "r"(b[0]), "r"(b[1]));
}

__device__ __forceinline__ void st4_tf(float* p, float4 v) {
    p[0] = __uint_as_float(f2tf(v.x));
    p[1] = __uint_as_float(f2tf(v.y));
    p[2] = __uint_as_float(f2tf(v.z));
    p[3] = __uint_as_float(f2tf(v.w));
}

__device__ __forceinline__ void cp16(float* dst, const float* src) {
    unsigned saddr = (unsigned)__cvta_generic_to_shared(dst);
    asm volatile("cp.async.cg.shared.global [%0], [%1], 16;\n"
                 :: "r"(saddr), "l"(src));
}

// ---------------------------------------------------------------------------
// GEMM: C[M,N] = A[M,K] @ B[N,K]^T  (row-major, K contiguous)
// BM=BN=128, BK=32, 256 threads (8 warps), tf32 mma m16n8k8.
// 2-stage cp.async pipeline; tf32 conversion done at fragment load.
// ---------------------------------------------------------------------------
#define STAGE_ELEMS (128 * 36)
#define GEMM_SMEM (4 * STAGE_ELEMS * 4)   // 2 stages x (A + B) = 73728 B

__global__ __launch_bounds__(256, 2) void gemm_tf32_kernel(
    float* __restrict__ C, const float* __restrict__ A, const float* __restrict__ B,
    int M, int N, int K)
{
    extern __shared__ float gsm[];
    float* sA = gsm;                       // [2][128*36]
    float* sB = gsm + 2 * STAGE_ELEMS;     // [2][128*36]

    // Swizzled CTA mapping (GROUP_M=8) for L2 reuse
    int num_m = M >> 7, num_n = N >> 7;
    const int GROUP = 8;
    int pid   = blockIdx.x;
    int width = GROUP * num_n;
    int gidx  = pid / width;
    int first_m = gidx * GROUP;
    int gsz   = min(GROUP, num_m - first_m);
    int pin   = pid % width;
    int pm    = first_m + (pin % gsz);
    int pn    = pin / gsz;

    int tid  = threadIdx.x;
    int lane = tid & 31, w = tid >> 5;
    int g = lane >> 2, c = lane & 3;
    int wm = (w >> 2) * 64;
    int wn = (w & 3) * 32;

    const float* Ab = A + (size_t)pm * 128 * K;
    const float* Bb = B + (size_t)pn * 128 * K;

    // thread's fixed load slots
    int lr  = tid >> 3;             // rows tid/8 .. +96 step 32? no: idx scheme below
    (void)lr;

    float acc[4][4][4];
    #pragma unroll
    for (int i = 0; i < 4; i++)
        #pragma unroll
        for (int j = 0; j < 4; j++)
            #pragma unroll
            for (int q = 0; q < 4; q++) acc[i][j][q] = 0.f;

    auto load_stage = [&](int buf, int kb) {
        float* dA = sA + buf * STAGE_ELEMS;
        float* dB = sB + buf * STAGE_ELEMS;
        #pragma unroll
        for (int i = 0; i < 4; i++) {
            int idx = tid + i * 256;       // 0..1023
            int r = idx >> 3, c4 = (idx & 7) << 2;
            cp16(&dA[r * 36 + c4], Ab + (size_t)r * K + kb + c4);
            cp16(&dB[r * 36 + c4], Bb + (size_t)r * K + kb + c4);
        }
    };

    int nt = K >> 5;
    load_stage(0, 0);
    asm volatile("cp.async.commit_group;\n");

    for (int t = 0; t < nt; t++) {
        if (t + 1 < nt) load_stage((t + 1) & 1, (t + 1) << 5);
        asm volatile("cp.async.commit_group;\n");
        asm volatile("cp.async.wait_group 1;\n");
        __syncthreads();

        const float* cA = sA + (t & 1) * STAGE_ELEMS;
        const float* cB = sB + (t & 1) * STAGE_ELEMS;

        #pragma unroll
        for (int ks = 0; ks < 4; ks++) {
            int k0 = ks * 8;
            unsigned afr[4][4], bfr[4][2];
            #pragma unroll
            for (int mi = 0; mi < 4; mi++) {
                int r0 = wm + mi * 16 + g;
                afr[mi][0] = f2tf(cA[r0 * 36 + k0 + c]);
                afr[mi][1] = f2tf(cA[(r0 + 8) * 36 + k0 + c]);
                afr[mi][2] = f2tf(cA[r0 * 36 + k0 + c + 4]);
                afr[mi][3] = f2tf(cA[(r0 + 8) * 36 + k0 + c + 4]);
            }
            #pragma unroll
            for (int nj = 0; nj < 4; nj++) {
                int rb = wn + nj * 8 + g;
                bfr[nj][0] = f2tf(cB[rb * 36 + k0 + c]);
                bfr[nj][1] = f2tf(cB[rb * 36 + k0 + c + 4]);
            }
            #pragma unroll
            for (int mi = 0; mi < 4; mi++)
                #pragma unroll
                for (int nj = 0; nj < 4; nj++)
                    mma_tf32(acc[mi][nj], afr[mi], bfr[nj]);
        }
        __syncthreads();
    }

    #pragma unroll
    for (int mi = 0; mi < 4; mi++) {
        int r0 = pm * 128 + wm + mi * 16 + g;
        #pragma unroll
        for (int nj = 0; nj < 4; nj++) {
            int col = pn * 128 + wn + nj * 8 + 2 * c;
            C[(size_t)r0 * N + col]           = acc[mi][nj][0];
            C[(size_t)r0 * N + col + 1]       = acc[mi][nj][1];
            C[(size_t)(r0 + 8) * N + col]     = acc[mi][nj][2];
            C[(size_t)(r0 + 8) * N + col + 1] = acc[mi][nj][3];
        }
    }
}

// ---------------------------------------------------------------------------
// RoPE in-place on Q and K sections of proj.
// ---------------------------------------------------------------------------
__global__ void rope_kernel(float* __restrict__ proj) {
    int idx = blockIdx.x * blockDim.x + threadIdx.x;
    if (idx >= 4096 * 32 * 64) return;
    int d   = idx & 63;
    int h   = (idx >> 6) & 31;
    int tok = idx >> 11;
    int pos = tok & 2047;

    float e   = (float)(2 * d) * (1.0f / 128.0f);
    float inv = 1.0f / powf(10000.0f, e);
    float ang = (float)pos * inv;
    float sn, cs;
    sincosf(ang, &sn, &cs);

    size_t base = (size_t)tok * 12288 + h * 128 + d;
    float q0 = proj[base], q1 = proj[base + 64];
    proj[base]      = q0 * cs - q1 * sn;
    proj[base + 64] = q1 * cs + q0 * sn;
    size_t kb = base + 4096;
    float k0 = proj[kb], k1 = proj[kb + 64];
    proj[kb]      = k0 * cs - k1 * sn;
    proj[kb + 64] = k1 * cs + k0 * sn;
}

// ---------------------------------------------------------------------------
// Flash attention (causal, online softmax, fp32 accum, tf32 mma).
// Grid: (32 m-tiles, 64 b*h). 128 threads (4 warps, 16 q-rows each).
// ---------------------------------------------------------------------------
#define QP 132
#define KPD 132
#define VP 136
#define FLASH_SMEM ((64 * QP + 64 * KPD + 64 * VP) * 4)

__global__ __launch_bounds__(128) void flash_kernel(
    const float* __restrict__ proj, float* __restrict__ outp)
{
    extern __shared__ float smem[];
    float* sQ = smem;
    float* sK = sQ + 64 * QP;
    float* sV = sK + 64 * KPD;

    int mt = blockIdx.x;
    int bh = blockIdx.y;
    int b  = bh >> 5, h = bh & 31;
    int tid = threadIdx.x, w = tid >> 5, lane = tid & 31;
    int g = lane >> 2, c = lane & 3;

    const float* base = proj + (size_t)b * 2048 * 12288 + h * 128;

    #pragma unroll
    for (int i = 0; i < 16; i++) {
        int idx = tid + i * 128;
        int r = idx >> 5, c4 = (idx & 31) << 2;
        float4 v = *reinterpret_cast<const float4*>(base + (size_t)(mt * 64 + r) * 12288 + c4);
        st4_tf(&sQ[r * QP + c4], v);
    }

    float o[16][4];
    #pragma unroll
    for (int i = 0; i < 16; i++)
        #pragma unroll
        for (int q = 0; q < 4; q++) o[i][q] = 0.f;
    float m0 = NEG_BIG, m1 = NEG_BIG, l0 = 0.f, l1 = 0.f;

    int qr0 = mt * 64 + w * 16 + g;
    int qr1 = qr0 + 8;
    const float SCALE = 0.08838834764831845f;  // 1/sqrt(128)

    for (int jt = 0; jt <= mt; jt++) {
        __syncthreads();
        #pragma unroll
        for (int i = 0; i < 16; i++) {
            int idx = tid + i * 128;
            int r = idx >> 5, c4 = (idx & 31) << 2;
            size_t row_off = (size_t)(jt * 64 + r) * 12288 + c4;
            float4 vk = *reinterpret_cast<const float4*>(base + 4096 + row_off);
            float4 vv = *reinterpret_cast<const float4*>(base + 8192 + row_off);
            st4_tf(&sK[r * KPD + c4], vk);
            st4_tf(&sV[r * VP + c4], vv);
        }
        __syncthreads();

        float s[8][4];
        #pragma unroll
        for (int nj = 0; nj < 8; nj++)
            #pragma unroll
            for (int q = 0; q < 4; q++) s[nj][q] = 0.f;

        int r0 = w * 16 + g;
        #pragma unroll
        for (int ks = 0; ks < 16; ks++) {
            int k0 = ks * 8;
            unsigned a[4];
            a[0] = __float_as_uint(sQ[r0 * QP + k0 + c]);
            a[1] = __float_as_uint(sQ[(r0 + 8) * QP + k0 + c]);
            a[2] = __float_as_uint(sQ[r0 * QP + k0 + c + 4]);
            a[3] = __float_as_uint(sQ[(r0 + 8) * QP + k0 + c + 4]);
            #pragma unroll
            for (int nj = 0; nj < 8; nj++) {
                unsigned bb[2];
                int rb = nj * 8 + g;
                bb[0] = __float_as_uint(sK[rb * KPD + k0 + c]);
                bb[1] = __float_as_uint(sK[rb * KPD + k0 + c + 4]);
                mma_tf32(s[nj], a, bb);
            }
        }

        #pragma unroll
        for (int nj = 0; nj < 8; nj++) {
            int c0 = jt * 64 + nj * 8 + 2 * c;
            int c1 = c0 + 1;
            s[nj][0] = (c0 <= qr0) ? s[nj][0] * SCALE : NEG_BIG;
            s[nj][1] = (c1 <= qr0) ? s[nj][1] * SCALE : NEG_BIG;
            s[nj][2] = (c0 <= qr1) ? s[nj][2] * SCALE : NEG_BIG;
            s[nj][3] = (c1 <= qr1) ? s[nj][3] * SCALE : NEG_BIG;
        }

        float rm0 = NEG_BIG, rm1 = NEG_BIG;
        #pragma unroll
        for (int nj = 0; nj < 8; nj++) {
            rm0 = fmaxf(rm0, fmaxf(s[nj][0], s[nj][1]));
            rm1 = fmaxf(rm1, fmaxf(s[nj][2], s[nj][3]));
        }
        rm0 = fmaxf(rm0, __shfl_xor_sync(0xffffffffu, rm0, 1));
        rm0 = fmaxf(rm0, __shfl_xor_sync(0xffffffffu, rm0, 2));
        rm1 = fmaxf(rm1, __shfl_xor_sync(0xffffffffu, rm1, 1));
        rm1 = fmaxf(rm1, __shfl_xor_sync(0xffffffffu, rm1, 2));

        float mn0 = fmaxf(m0, rm0), mn1 = fmaxf(m1, rm1);
        float al0 = __expf(m0 - mn0), al1 = __expf(m1 - mn1);
        m0 = mn0; m1 = mn1;

        float rs0 = 0.f, rs1 = 0.f;
        #pragma unroll
        for (int nj = 0; nj < 8; nj++) {
            s[nj][0] = __expf(s[nj][0] - m0);
            s[nj][1] = __expf(s[nj][1] - m0);
            s[nj][2] = __expf(s[nj][2] - m1);
            s[nj][3] = __expf(s[nj][3] - m1);
            rs0 += s[nj][0] + s[nj][1];
            rs1 += s[nj][2] + s[nj][3];
        }
        rs0 += __shfl_xor_sync(0xffffffffu, rs0, 1);
        rs0 += __shfl_xor_sync(0xffffffffu, rs0, 2);
        rs1 += __shfl_xor_sync(0xffffffffu, rs1, 1);
        rs1 += __shfl_xor_sync(0xffffffffu, rs1, 2);
        l0 = l0 * al0 + rs0;
        l1 = l1 * al1 + rs1;

        #pragma unroll
        for (int nf = 0; nf < 16; nf++) {
            o[nf][0] *= al0; o[nf][1] *= al0;
            o[nf][2] *= al1; o[nf][3] *= al1;
        }

        int src  = (lane & ~3) | (c >> 1);
        int src2 = src + 2;
        bool odd = (c & 1) != 0;
        #pragma unroll
        for (int kk = 0; kk < 8; kk++) {
            float e0 = __shfl_sync(0xffffffffu, s[kk][0], src);
            float f0 = __shfl_sync(0xffffffffu, s[kk][1], src);
            float e1 = __shfl_sync(0xffffffffu, s[kk][2], src);
            float f1 = __shfl_sync(0xffffffffu, s[kk][3], src);
            float e2 = __shfl_sync(0xffffffffu, s[kk][0], src2);
            float f2 = __shfl_sync(0xffffffffu, s[kk][1], src2);
            float e3 = __shfl_sync(0xffffffffu, s[kk][2], src2);
            float f3 = __shfl_sync(0xffffffffu, s[kk][3], src2);
            unsigned a[4];
            a[0] = f2tf(odd ? f0 : e0);
            a[1] = f2tf(odd ? f1 : e1);
            a[2] = f2tf(odd ? f2 : e2);
            a[3] = f2tf(odd ? f3 : e3);
            #pragma unroll
            for (int nf = 0; nf < 16; nf++) {
                unsigned bb[2];
                bb[0] = __float_as_uint(sV[(kk * 8 + c) * VP + nf * 8 + g]);
                bb[1] = __float_as_uint(sV[(kk * 8 + c + 4) * VP + nf * 8 + g]);
                mma_tf32(o[nf], a, bb);
            }
        }
    }

    float i0 = 1.0f / l0, i1 = 1.0f / l1;
    int tk0 = b * 2048 + mt * 64 + w * 16 + g;
    int tk1 = tk0 + 8;
    size_t ob0 = (size_t)tk0 * 4096 + h * 128;
    size_t ob1 = (size_t)tk1 * 4096 + h * 128;
    #pragma unroll
    for (int nf = 0; nf < 16; nf++) {
        int col = nf * 8 + 2 * c;
        outp[ob0 + col]     = o[nf][0] * i0;
        outp[ob0 + col + 1] = o[nf][1] * i0;
        outp[ob1 + col]     = o[nf][2] * i1;
        outp[ob1 + col + 1] = o[nf][3] * i1;
    }
}

// ---------------------------------------------------------------------------
extern "C" void kernel_launch(void* const* d_in, const int* in_sizes, int n_in,
                              void* d_out, int out_size)
{
    (void)in_sizes; (void)n_in; (void)out_size;
    const float* X  = (const float*)d_in[0];  // hidden_states [2,2048,4096]
    const float* Wp = (const float*)d_in[3];  // W_pack [12288,4096]
    const float* Wo = (const float*)d_in[4];  // W_o    [4096,4096]
    float* out = (float*)d_out;

    float *proj = nullptr, *attn = nullptr;
    cudaGetSymbolAddress((void**)&proj, g_proj);
    cudaGetSymbolAddress((void**)&attn, g_attn);

    cudaFuncSetAttribute(gemm_tf32_kernel, cudaFuncAttributeMaxDynamicSharedMemorySize, GEMM_SMEM);
    cudaFuncSetAttribute(flash_kernel, cudaFuncAttributeMaxDynamicSharedMemorySize, FLASH_SMEM);

    // 1) QKV projection: proj = X @ Wp^T   (M=4096, N=12288, K=4096)
    gemm_tf32_kernel<<<32 * 96, 256, GEMM_SMEM>>>(proj, X, Wp, 4096, 12288, 4096);

    // 2) RoPE in-place on Q,K
    rope_kernel<<<(4096 * 32 * 64) / 256, 256>>>(proj);

    // 3) Flash attention -> attn [4096, 4096]
    flash_kernel<<<dim3(32, 64), 128, FLASH_SMEM>>>(proj, attn);

    // 4) Output projection: out = attn @ Wo^T  (M=4096, N=4096, K=4096)
    gemm_tf32_kernel<<<32 * 32, 256, GEMM_SMEM>>>(out, attn, Wo, 4096, 4096, 4096);
}

// round 7
// speedup vs baseline: 1.7213x; 1.0780x over previous
#include <cuda_runtime.h>
#include <cstdint>
#include <math.h>

// Problem constants: B=2, S=2048, HIDDEN=4096, NH=32, D=128
// proj layout: [token(4096), 12288] cols [0,4096)=Q, [4096,8192)=K, [8192,12288)=V
// attn layout: [token(4096), 4096]

static __device__ float g_proj[(size_t)4096 * 12288];   // 201 MB scratch
static __device__ float g_attn[(size_t)4096 * 4096];    //  67 MB scratch

#define NEG_BIG (-1e30f)

__device__ __forceinline__ unsigned f2tf(float x) {
    unsigned u;
    asm("cvt.rna.tf32.f32 %0, %1;" : "=r"(u) : "f"(x));
    return u;
}

__device__ __forceinline__ void mma_tf32(float* d, const unsigned* a, const unsigned* b) {
    asm volatile(
        "mma.sync.aligned.m16n8k8.row.col.f32.tf32.tf32.f32 "
        "{%0,%1,%2,%3}, {%4,%5,%6,%7}, {%8,%9}, {%0,%1,%2,%3};\n"
        : "+f"(d[0]), "+f"(d[1]), "+f"(d[2]), "+f"(d[3])
        : "r"(a[0]), "r"(a[1]), "r"(a[2]), "r"(a[3]), "r"(b[0]), "r"(b[1]));
}

__device__ __forceinline__ void st4_tf(float* p, float4 v) {
    p[0] = __uint_as_float(f2tf(v.x));
    p[1] = __uint_as_float(f2tf(v.y));
    p[2] = __uint_as_float(f2tf(v.z));
    p[3] = __uint_as_float(f2tf(v.w));
}

__device__ __forceinline__ void cp16(float* dst, const float* src) {
    unsigned saddr = (unsigned)__cvta_generic_to_shared(dst);
    asm volatile("cp.async.cg.shared.global [%0], [%1], 16;\n"
                 :: "r"(saddr), "l"(src));
}

// ---------------------------------------------------------------------------
// GEMM: C[M,N] = A[M,K] @ B[N,K]^T  (row-major, K contiguous)
// BM=BN=128, BK=32, 256 threads (8 warps), tf32 mma m16n8k8.
// 2-stage cp.async pipeline; tf32 conversion at fragment load.
// ---------------------------------------------------------------------------
#define STAGE_ELEMS (128 * 36)
#define GEMM_SMEM (4 * STAGE_ELEMS * 4)   // 2 stages x (A + B) = 73728 B

__global__ __launch_bounds__(256, 2) void gemm_tf32_kernel(
    float* __restrict__ C, const float* __restrict__ A, const float* __restrict__ B,
    int M, int N, int K)
{
    extern __shared__ float gsm[];
    float* sA = gsm;                       // [2][128*36]
    float* sB = gsm + 2 * STAGE_ELEMS;     // [2][128*36]

    int num_m = M >> 7, num_n = N >> 7;
    const int GROUP = 8;
    int pid   = blockIdx.x;
    int width = GROUP * num_n;
    int gidx  = pid / width;
    int first_m = gidx * GROUP;
    int gsz   = min(GROUP, num_m - first_m);
    int pin   = pid % width;
    int pm    = first_m + (pin % gsz);
    int pn    = pin / gsz;

    int tid  = threadIdx.x;
    int lane = tid & 31, w = tid >> 5;
    int g = lane >> 2, c = lane & 3;
    int wm = (w >> 2) * 64;
    int wn = (w & 3) * 32;

    const float* Ab = A + (size_t)pm * 128 * K;
    const float* Bb = B + (size_t)pn * 128 * K;

    float acc[4][4][4];
    #pragma unroll
    for (int i = 0; i < 4; i++)
        #pragma unroll
        for (int j = 0; j < 4; j++)
            #pragma unroll
            for (int q = 0; q < 4; q++) acc[i][j][q] = 0.f;

    auto load_stage = [&](int buf, int kb) {
        float* dA = sA + buf * STAGE_ELEMS;
        float* dB = sB + buf * STAGE_ELEMS;
        #pragma unroll
        for (int i = 0; i < 4; i++) {
            int idx = tid + i * 256;
            int r = idx >> 3, c4 = (idx & 7) << 2;
            cp16(&dA[r * 36 + c4], Ab + (size_t)r * K + kb + c4);
            cp16(&dB[r * 36 + c4], Bb + (size_t)r * K + kb + c4);
        }
    };

    int nt = K >> 5;
    load_stage(0, 0);
    asm volatile("cp.async.commit_group;\n");

    for (int t = 0; t < nt; t++) {
        if (t + 1 < nt) load_stage((t + 1) & 1, (t + 1) << 5);
        asm volatile("cp.async.commit_group;\n");
        asm volatile("cp.async.wait_group 1;\n");
        __syncthreads();

        const float* cA = sA + (t & 1) * STAGE_ELEMS;
        const float* cB = sB + (t & 1) * STAGE_ELEMS;

        #pragma unroll
        for (int ks = 0; ks < 4; ks++) {
            int k0 = ks * 8;
            unsigned afr[4][4], bfr[4][2];
            #pragma unroll
            for (int mi = 0; mi < 4; mi++) {
                int r0 = wm + mi * 16 + g;
                afr[mi][0] = f2tf(cA[r0 * 36 + k0 + c]);
                afr[mi][1] = f2tf(cA[(r0 + 8) * 36 + k0 + c]);
                afr[mi][2] = f2tf(cA[r0 * 36 + k0 + c + 4]);
                afr[mi][3] = f2tf(cA[(r0 + 8) * 36 + k0 + c + 4]);
            }
            #pragma unroll
            for (int nj = 0; nj < 4; nj++) {
                int rb = wn + nj * 8 + g;
                bfr[nj][0] = f2tf(cB[rb * 36 + k0 + c]);
                bfr[nj][1] = f2tf(cB[rb * 36 + k0 + c + 4]);
            }
            #pragma unroll
            for (int mi = 0; mi < 4; mi++)
                #pragma unroll
                for (int nj = 0; nj < 4; nj++)
                    mma_tf32(acc[mi][nj], afr[mi], bfr[nj]);
        }
        __syncthreads();
    }

    #pragma unroll
    for (int mi = 0; mi < 4; mi++) {
        int r0 = pm * 128 + wm + mi * 16 + g;
        #pragma unroll
        for (int nj = 0; nj < 4; nj++) {
            int col = pn * 128 + wn + nj * 8 + 2 * c;
            *reinterpret_cast<float2*>(&C[(size_t)r0 * N + col]) =
                make_float2(acc[mi][nj][0], acc[mi][nj][1]);
            *reinterpret_cast<float2*>(&C[(size_t)(r0 + 8) * N + col]) =
                make_float2(acc[mi][nj][2], acc[mi][nj][3]);
        }
    }
}

// ---------------------------------------------------------------------------
// RoPE in-place on Q and K sections of proj.
// ---------------------------------------------------------------------------
__global__ void rope_kernel(float* __restrict__ proj) {
    int idx = blockIdx.x * blockDim.x + threadIdx.x;
    if (idx >= 4096 * 32 * 64) return;
    int d   = idx & 63;
    int h   = (idx >> 6) & 31;
    int tok = idx >> 11;
    int pos = tok & 2047;

    float e   = (float)(2 * d) * (1.0f / 128.0f);
    float inv = 1.0f / powf(10000.0f, e);
    float ang = (float)pos * inv;
    float sn, cs;
    sincosf(ang, &sn, &cs);

    size_t base = (size_t)tok * 12288 + h * 128 + d;
    float q0 = proj[base], q1 = proj[base + 64];
    proj[base]      = q0 * cs - q1 * sn;
    proj[base + 64] = q1 * cs + q0 * sn;
    size_t kb = base + 4096;
    float k0 = proj[kb], k1 = proj[kb + 64];
    proj[kb]      = k0 * cs - k1 * sn;
    proj[kb + 64] = k1 * cs + k0 * sn;
}

// ---------------------------------------------------------------------------
// Flash attention (causal, online softmax, fp32 accum, tf32 mma).
// BM=128 q rows, BN=64 kv cols, 256 threads (8 warps, 16 q-rows each).
// 2-stage cp.async double-buffer on K/V. Grid: (16 m-tiles, 64 b*h).
// ---------------------------------------------------------------------------
#define QP 132
#define KP 132
#define VP 136
#define FLASH_SMEM ((128 * QP + 2 * 64 * KP + 2 * 64 * VP) * 4)   // 204800 B

__global__ __launch_bounds__(256, 1) void flash_kernel(
    const float* __restrict__ proj, float* __restrict__ outp)
{
    extern __shared__ float smem[];
    float* sQ = smem;                  // [128][QP]  (tf32-converted)
    float* sK = sQ + 128 * QP;         // [2][64][KP] (raw fp32)
    float* sV = sK + 2 * 64 * KP;      // [2][64][VP] (raw fp32)

    int mt = 15 - blockIdx.x;          // heaviest tiles first
    int bh = blockIdx.y;
    int b  = bh >> 5, h = bh & 31;
    int tid = threadIdx.x, w = tid >> 5, lane = tid & 31;
    int g = lane >> 2, c = lane & 3;

    const float* base = proj + (size_t)b * 2048 * 12288 + h * 128;

    auto load_kv = [&](int buf, int jt) {
        float* dK = sK + buf * 64 * KP;
        float* dV = sV + buf * 64 * VP;
        #pragma unroll
        for (int i = 0; i < 8; i++) {
            int idx = tid + i * 256;           // 0..2047
            int r = idx >> 5, c4 = (idx & 31) << 2;
            size_t off = (size_t)(jt * 64 + r) * 12288 + c4;
            cp16(&dK[r * KP + c4], base + 4096 + off);
            cp16(&dV[r * VP + c4], base + 8192 + off);
        }
    };

    int jtmax = 2 * mt + 1;
    load_kv(0, 0);
    asm volatile("cp.async.commit_group;\n");

    // Q tile [128,128] once (tf32-converted); LDG latency overlaps the cp.async above
    #pragma unroll
    for (int i = 0; i < 16; i++) {
        int idx = tid + i * 256;
        int r = idx >> 5, c4 = (idx & 31) << 2;
        float4 v = *reinterpret_cast<const float4*>(base + (size_t)(mt * 128 + r) * 12288 + c4);
        st4_tf(&sQ[r * QP + c4], v);
    }

    float o[16][4];
    #pragma unroll
    for (int i = 0; i < 16; i++)
        #pragma unroll
        for (int q = 0; q < 4; q++) o[i][q] = 0.f;
    float m0 = NEG_BIG, m1 = NEG_BIG, l0 = 0.f, l1 = 0.f;

    int qr0 = mt * 128 + w * 16 + g;
    int qr1 = qr0 + 8;
    const float SCALE = 0.08838834764831845f;  // 1/sqrt(128)

    for (int jt = 0; jt <= jtmax; jt++) {
        if (jt < jtmax) load_kv((jt + 1) & 1, jt + 1);
        asm volatile("cp.async.commit_group;\n");
        asm volatile("cp.async.wait_group 1;\n");
        __syncthreads();

        const float* cK = sK + (jt & 1) * 64 * KP;
        const float* cV = sV + (jt & 1) * 64 * VP;

        // S = Q @ K^T : per warp 16x64
        float s[8][4];
        #pragma unroll
        for (int nj = 0; nj < 8; nj++)
            #pragma unroll
            for (int q = 0; q < 4; q++) s[nj][q] = 0.f;

        int r0 = w * 16 + g;
        #pragma unroll
        for (int ks = 0; ks < 16; ks++) {
            int k0 = ks * 8;
            unsigned a[4];
            a[0] = __float_as_uint(sQ[r0 * QP + k0 + c]);
            a[1] = __float_as_uint(sQ[(r0 + 8) * QP + k0 + c]);
            a[2] = __float_as_uint(sQ[r0 * QP + k0 + c + 4]);
            a[3] = __float_as_uint(sQ[(r0 + 8) * QP + k0 + c + 4]);
            #pragma unroll
            for (int nj = 0; nj < 8; nj++) {
                unsigned bb[2];
                int rb = nj * 8 + g;
                bb[0] = f2tf(cK[rb * KP + k0 + c]);
                bb[1] = f2tf(cK[rb * KP + k0 + c + 4]);
                mma_tf32(s[nj], a, bb);
            }
        }

        // scale (+ causal mask only on the two diagonal tiles)
        if (jt >= 2 * mt) {
            #pragma unroll
            for (int nj = 0; nj < 8; nj++) {
                int c0 = jt * 64 + nj * 8 + 2 * c;
                int c1 = c0 + 1;
                s[nj][0] = (c0 <= qr0) ? s[nj][0] * SCALE : NEG_BIG;
                s[nj][1] = (c1 <= qr0) ? s[nj][1] * SCALE : NEG_BIG;
                s[nj][2] = (c0 <= qr1) ? s[nj][2] * SCALE : NEG_BIG;
                s[nj][3] = (c1 <= qr1) ? s[nj][3] * SCALE : NEG_BIG;
            }
        } else {
            #pragma unroll
            for (int nj = 0; nj < 8; nj++) {
                s[nj][0] *= SCALE; s[nj][1] *= SCALE;
                s[nj][2] *= SCALE; s[nj][3] *= SCALE;
            }
        }

        // row max
        float rm0 = NEG_BIG, rm1 = NEG_BIG;
        #pragma unroll
        for (int nj = 0; nj < 8; nj++) {
            rm0 = fmaxf(rm0, fmaxf(s[nj][0], s[nj][1]));
            rm1 = fmaxf(rm1, fmaxf(s[nj][2], s[nj][3]));
        }
        rm0 = fmaxf(rm0, __shfl_xor_sync(0xffffffffu, rm0, 1));
        rm0 = fmaxf(rm0, __shfl_xor_sync(0xffffffffu, rm0, 2));
        rm1 = fmaxf(rm1, __shfl_xor_sync(0xffffffffu, rm1, 1));
        rm1 = fmaxf(rm1, __shfl_xor_sync(0xffffffffu, rm1, 2));

        float mn0 = fmaxf(m0, rm0), mn1 = fmaxf(m1, rm1);
        float al0 = __expf(m0 - mn0), al1 = __expf(m1 - mn1);
        m0 = mn0; m1 = mn1;

        // P = exp(S - m), row sums
        float rs0 = 0.f, rs1 = 0.f;
        #pragma unroll
        for (int nj = 0; nj < 8; nj++) {
            s[nj][0] = __expf(s[nj][0] - m0);
            s[nj][1] = __expf(s[nj][1] - m0);
            s[nj][2] = __expf(s[nj][2] - m1);
            s[nj][3] = __expf(s[nj][3] - m1);
            rs0 += s[nj][0] + s[nj][1];
            rs1 += s[nj][2] + s[nj][3];
        }
        rs0 += __shfl_xor_sync(0xffffffffu, rs0, 1);
        rs0 += __shfl_xor_sync(0xffffffffu, rs0, 2);
        rs1 += __shfl_xor_sync(0xffffffffu, rs1, 1);
        rs1 += __shfl_xor_sync(0xffffffffu, rs1, 2);
        l0 = l0 * al0 + rs0;
        l1 = l1 * al1 + rs1;

        // rescale O accumulators
        #pragma unroll
        for (int nf = 0; nf < 16; nf++) {
            o[nf][0] *= al0; o[nf][1] *= al0;
            o[nf][2] *= al1; o[nf][3] *= al1;
        }

        // O += P @ V : C-frag -> A-frag conversion via shuffles
        int src  = (lane & ~3) | (c >> 1);
        int src2 = src + 2;
        bool odd = (c & 1) != 0;
        #pragma unroll
        for (int kk = 0; kk < 8; kk++) {
            float e0 = __shfl_sync(0xffffffffu, s[kk][0], src);
            float f0 = __shfl_sync(0xffffffffu, s[kk][1], src);
            float e1 = __shfl_sync(0xffffffffu, s[kk][2], src);
            float f1 = __shfl_sync(0xffffffffu, s[kk][3], src);
            float e2 = __shfl_sync(0xffffffffu, s[kk][0], src2);
            float f2 = __shfl_sync(0xffffffffu, s[kk][1], src2);
            float e3 = __shfl_sync(0xffffffffu, s[kk][2], src2);
            float f3 = __shfl_sync(0xffffffffu, s[kk][3], src2);
            unsigned a[4];
            a[0] = f2tf(odd ? f0 : e0);
            a[1] = f2tf(odd ? f1 : e1);
            a[2] = f2tf(odd ? f2 : e2);
            a[3] = f2tf(odd ? f3 : e3);
            #pragma unroll
            for (int nf = 0; nf < 16; nf++) {
                unsigned bb[2];
                bb[0] = f2tf(cV[(kk * 8 + c) * VP + nf * 8 + g]);
                bb[1] = f2tf(cV[(kk * 8 + c + 4) * VP + nf * 8 + g]);
                mma_tf32(o[nf], a, bb);
            }
        }
        __syncthreads();
    }

    // Normalize and store
    float i0 = 1.0f / l0, i1 = 1.0f / l1;
    int tk0 = b * 2048 + mt * 128 + w * 16 + g;
    int tk1 = tk0 + 8;
    size_t ob0 = (size_t)tk0 * 4096 + h * 128;
    size_t ob1 = (size_t)tk1 * 4096 + h * 128;
    #pragma unroll
    for (int nf = 0; nf < 16; nf++) {
        int col = nf * 8 + 2 * c;
        *reinterpret_cast<float2*>(&outp[ob0 + col]) =
            make_float2(o[nf][0] * i0, o[nf][1] * i0);
        *reinterpret_cast<float2*>(&outp[ob1 + col]) =
            make_float2(o[nf][2] * i1, o[nf][3] * i1);
    }
}

// ---------------------------------------------------------------------------
extern "C" void kernel_launch(void* const* d_in, const int* in_sizes, int n_in,
                              void* d_out, int out_size)
{
    (void)in_sizes; (void)n_in; (void)out_size;
    const float* X  = (const float*)d_in[0];  // hidden_states [2,2048,4096]
    const float* Wp = (const float*)d_in[3];  // W_pack [12288,4096]
    const float* Wo = (const float*)d_in[4];  // W_o    [4096,4096]
    float* out = (float*)d_out;

    float *proj = nullptr, *attn = nullptr;
    cudaGetSymbolAddress((void**)&proj, g_proj);
    cudaGetSymbolAddress((void**)&attn, g_attn);

    cudaFuncSetAttribute(gemm_tf32_kernel, cudaFuncAttributeMaxDynamicSharedMemorySize, GEMM_SMEM);
    cudaFuncSetAttribute(flash_kernel, cudaFuncAttributeMaxDynamicSharedMemorySize, FLASH_SMEM);

    // 1) QKV projection: proj = X @ Wp^T   (M=4096, N=12288, K=4096)
    gemm_tf32_kernel<<<32 * 96, 256, GEMM_SMEM>>>(proj, X, Wp, 4096, 12288, 4096);

    // 2) RoPE in-place on Q,K
    rope_kernel<<<(4096 * 32 * 64) / 256, 256>>>(proj);

    // 3) Flash attention -> attn [4096, 4096]
    flash_kernel<<<dim3(16, 64), 256, FLASH_SMEM>>>(proj, attn);

    // 4) Output projection: out = attn @ Wo^T  (M=4096, N=4096, K=4096)
    gemm_tf32_kernel<<<32 * 32, 256, GEMM_SMEM>>>(out, attn, Wo, 4096, 4096, 4096);
}